// round 12
// baseline (speedup 1.0000x reference)
#include <cuda_runtime.h>
#include <cuda_fp16.h>

#define N_NODES 50000
#define N_EDGES 640000
#define NB_CNT ((N_NODES + 255) / 256)   // 196 scan blocks
// IN_DIM = OUT_DIM = 128, H = 4, D = 32

// ---------------- scratch (device globals; no allocation allowed) ------------
__device__ __align__(16) __half g_Wh[N_NODES * 128];   // fp16 Wh
__device__ __align__(16) float g_sl[N_NODES * 4];
__device__ __align__(16) float g_sr[N_NODES * 4];
__device__ __align__(16) float g_sattn[N_EDGES * 4];   // attn logits, dst-sorted
__device__ int g_ssrc[N_EDGES];                        // src node, dst-sorted
__device__ int g_cnt[N_NODES];
__device__ int g_offs[N_NODES + 1];
__device__ int g_cursor[N_NODES];
__device__ unsigned long long g_scanstate[NB_CNT];     // flag<<62 | sum

// ---------------- K0: zero counters + scan state -----------------------------
__global__ void __launch_bounds__(256) k_zero() {
    int i = blockIdx.x * blockDim.x + threadIdx.x;
    if (i < N_NODES) g_cnt[i] = 0;
    if (i < NB_CNT)  g_scanstate[i] = 0ull;
}

// ---------------- K1: count incoming edges per node ---------------------------
__global__ void __launch_bounds__(256) k_count(const int* __restrict__ ei) {
    int e = blockIdx.x * blockDim.x + threadIdx.x;
    if (e < N_EDGES) atomicAdd(&g_cnt[ei[N_EDGES + e]], 1);
}

// ---------------- K2: single-kernel exclusive scan (decoupled lookback) ------
__global__ void __launch_bounds__(256) k_scan_fused() {
    __shared__ int swsum[8];
    __shared__ int s_running;
    const int t = threadIdx.x, b = blockIdx.x;
    const int lane = t & 31, w = t >> 5;
    const int i = b * 256 + t;

    int c = (i < N_NODES) ? g_cnt[i] : 0;
    // warp inclusive scan
    int x = c;
#pragma unroll
    for (int o = 1; o < 32; o <<= 1) {
        int v = __shfl_up_sync(0xffffffffu, x, o);
        if (lane >= o) x += v;
    }
    if (lane == 31) swsum[w] = x;
    __syncthreads();
    if (w == 0) {
        int y = (lane < 8) ? swsum[lane] : 0;
#pragma unroll
        for (int o = 1; o < 8; o <<= 1) {
            int v = __shfl_up_sync(0xffffffffu, y, o);
            if (lane >= o) y += v;
        }
        if (lane < 8) swsum[lane] = y;
    }
    __syncthreads();
    const int incl  = x + (w > 0 ? swsum[w - 1] : 0);   // inclusive within block
    const int total = swsum[7];

    if (t == 0) {
        unsigned long long pub =
            ((unsigned long long)(b == 0 ? 2 : 1) << 62) | (unsigned)total;
        __threadfence();
        atomicExch(&g_scanstate[b], pub);

        int run = 0;
        if (b > 0) {
            int j = b - 1;
            while (true) {
                unsigned long long s = atomicAdd(&g_scanstate[j], 0ull);
                unsigned f = (unsigned)(s >> 62);
                if (f == 0) continue;
                run += (int)(s & 0xffffffffull);
                if (f == 2) break;
                j--;
            }
            unsigned long long pub2 = (2ull << 62) | (unsigned)(run + total);
            atomicExch(&g_scanstate[b], pub2);
        }
        s_running = run;
    }
    __syncthreads();

    int off = s_running + incl - c;   // exclusive prefix
    if (i < N_NODES) {
        g_offs[i]   = off;
        g_cursor[i] = off;
    }
    if (b == gridDim.x - 1 && t == 255) g_offs[N_NODES] = s_running + incl;
}

// ---------------- K3: Wh = h @ W^T via fp16 MMA, sides fused in epilogue -----
__device__ __forceinline__ unsigned smem_u32(const void* p) {
    return (unsigned)__cvta_generic_to_shared(p);
}

__global__ void __launch_bounds__(256) k_gemm(const float* __restrict__ h,
                                              const float* __restrict__ W,
                                              const float* __restrict__ a) {
    __shared__ __half As[128 * 72];   // padded rows: 72 halfs = 144B (16B mult)
    __shared__ __half Bs[128 * 72];   // Bs[n][k] = W[n][k]
    const int tid  = threadIdx.x;
    const int lane = tid & 31;
    const int warp = tid >> 5;
    const int m0 = (warp >> 1) * 32;      // warp row base within block
    const int n0 = (warp & 1) * 64;       // warp col base within block
    const int rowbase = blockIdx.x * 128;

    float acc[2][8][4];
#pragma unroll
    for (int mt = 0; mt < 2; mt++)
#pragma unroll
        for (int nt = 0; nt < 8; nt++)
#pragma unroll
            for (int q = 0; q < 4; q++) acc[mt][nt][q] = 0.0f;

    const float4* h4 = reinterpret_cast<const float4*>(h);
    const float4* W4 = reinterpret_cast<const float4*>(W);

    for (int phase = 0; phase < 2; phase++) {
        __syncthreads();
        {
            int r  = tid >> 4;       // 0..15
            int c4 = tid & 15;       // float4 index within 64 cols
#pragma unroll
            for (int it = 0; it < 8; it++) {
                int row  = r + it * 16;
                int grow = rowbase + row;
                if (grow >= N_NODES) grow = N_NODES - 1;
                float4 v = h4[grow * 32 + phase * 16 + c4];
                __half2* dst = reinterpret_cast<__half2*>(&As[row * 72 + c4 * 4]);
                dst[0] = __floats2half2_rn(v.x, v.y);
                dst[1] = __floats2half2_rn(v.z, v.w);
            }
#pragma unroll
            for (int it = 0; it < 8; it++) {
                int n = r + it * 16;
                float4 v = W4[n * 32 + phase * 16 + c4];
                __half2* dst = reinterpret_cast<__half2*>(&Bs[n * 72 + c4 * 4]);
                dst[0] = __floats2half2_rn(v.x, v.y);
                dst[1] = __floats2half2_rn(v.z, v.w);
            }
        }
        __syncthreads();

#pragma unroll
        for (int ks = 0; ks < 4; ks++) {
            const int k = ks * 16;
            unsigned af[2][4];
#pragma unroll
            for (int mt = 0; mt < 2; mt++) {
                int row = m0 + mt * 16 + (lane & 15);
                int col = k + (lane >> 4) * 8;
                unsigned addr = smem_u32(&As[row * 72 + col]);
                asm volatile(
                    "ldmatrix.sync.aligned.m8n8.x4.shared.b16 {%0,%1,%2,%3}, [%4];"
                    : "=r"(af[mt][0]), "=r"(af[mt][1]), "=r"(af[mt][2]), "=r"(af[mt][3])
                    : "r"(addr));
            }
            unsigned bf[8][2];
#pragma unroll
            for (int nt2 = 0; nt2 < 4; nt2++) {
                int n   = n0 + nt2 * 16 + (lane >> 4) * 8 + (lane & 7);
                int col = k + ((lane >> 3) & 1) * 8;
                unsigned addr = smem_u32(&Bs[n * 72 + col]);
                unsigned r0, r1, r2, r3;
                asm volatile(
                    "ldmatrix.sync.aligned.m8n8.x4.shared.b16 {%0,%1,%2,%3}, [%4];"
                    : "=r"(r0), "=r"(r1), "=r"(r2), "=r"(r3)
                    : "r"(addr));
                bf[nt2 * 2][0]     = r0; bf[nt2 * 2][1]     = r1;
                bf[nt2 * 2 + 1][0] = r2; bf[nt2 * 2 + 1][1] = r3;
            }
#pragma unroll
            for (int mt = 0; mt < 2; mt++)
#pragma unroll
                for (int nt = 0; nt < 8; nt++) {
                    asm volatile(
                        "mma.sync.aligned.m16n8k16.row.col.f32.f16.f16.f32 "
                        "{%0,%1,%2,%3}, {%4,%5,%6,%7}, {%8,%9}, {%0,%1,%2,%3};"
                        : "+f"(acc[mt][nt][0]), "+f"(acc[mt][nt][1]),
                          "+f"(acc[mt][nt][2]), "+f"(acc[mt][nt][3])
                        : "r"(af[mt][0]), "r"(af[mt][1]), "r"(af[mt][2]), "r"(af[mt][3]),
                          "r"(bf[nt][0]), "r"(bf[nt][1]));
                }
        }
    }

    // ---- epilogue: Wh fp16 stores + fused s_l/s_r from fp32 accumulators ----
    // frag layout: d0,d1 -> row lane/4, cols 2(lane%4)+{0,1}; d2,d3 -> row+8.
    const int h0 = (warp & 1) * 2;    // this warp's heads: h0, h0+1
    const int cb = (lane & 3) * 2;

#pragma unroll
    for (int mt = 0; mt < 2; mt++) {
        int r0 = rowbase + m0 + mt * 16 + (lane >> 2);
        int r1 = r0 + 8;
#pragma unroll
        for (int nt = 0; nt < 8; nt++) {
            int col = n0 + nt * 8 + cb;
            if (r0 < N_NODES)
                *reinterpret_cast<__half2*>(&g_Wh[r0 * 128 + col]) =
                    __floats2half2_rn(acc[mt][nt][0], acc[mt][nt][1]);
            if (r1 < N_NODES)
                *reinterpret_cast<__half2*>(&g_Wh[r1 * 128 + col]) =
                    __floats2half2_rn(acc[mt][nt][2], acc[mt][nt][3]);
        }

        // sides partials: index [hi] = head h0+hi
        float sl[2] = {0.f, 0.f}, sr[2] = {0.f, 0.f};   // row r0
        float ul[2] = {0.f, 0.f}, ur[2] = {0.f, 0.f};   // row r1
#pragma unroll
        for (int nt = 0; nt < 8; nt++) {
            int hi = nt >> 2;
            int hh = h0 + hi;
            int d  = (nt & 3) * 8 + cb;                 // dim within head
            float al0 = a[hh * 64 + d],      al1 = a[hh * 64 + d + 1];
            float ar0 = a[hh * 64 + 32 + d], ar1 = a[hh * 64 + 32 + d + 1];
            sl[hi] += acc[mt][nt][0] * al0 + acc[mt][nt][1] * al1;
            sr[hi] += acc[mt][nt][0] * ar0 + acc[mt][nt][1] * ar1;
            ul[hi] += acc[mt][nt][2] * al0 + acc[mt][nt][3] * al1;
            ur[hi] += acc[mt][nt][2] * ar0 + acc[mt][nt][3] * ar1;
        }
#pragma unroll
        for (int o = 1; o < 4; o <<= 1) {
#pragma unroll
            for (int hi = 0; hi < 2; hi++) {
                sl[hi] += __shfl_xor_sync(0xffffffffu, sl[hi], o);
                sr[hi] += __shfl_xor_sync(0xffffffffu, sr[hi], o);
                ul[hi] += __shfl_xor_sync(0xffffffffu, ul[hi], o);
                ur[hi] += __shfl_xor_sync(0xffffffffu, ur[hi], o);
            }
        }
        if ((lane & 3) == 0) {
            if (r0 < N_NODES) {
                g_sl[r0 * 4 + h0]     = sl[0];
                g_sl[r0 * 4 + h0 + 1] = sl[1];
                g_sr[r0 * 4 + h0]     = sr[0];
                g_sr[r0 * 4 + h0 + 1] = sr[1];
            }
            if (r1 < N_NODES) {
                g_sl[r1 * 4 + h0]     = ul[0];
                g_sl[r1 * 4 + h0 + 1] = ul[1];
                g_sr[r1 * 4 + h0]     = ur[0];
                g_sr[r1 * 4 + h0 + 1] = ur[1];
            }
        }
    }
}

// ---------------- K4: attention logits, written in dst-sorted order ----------
__global__ void __launch_bounds__(256) k_attn_fill(const int* __restrict__ ei,
                                                   const float* __restrict__ ef,
                                                   const float* __restrict__ We) {
    __shared__ float sWe[64];
    if (threadIdx.x < 64) sWe[threadIdx.x] = We[threadIdx.x];
    __syncthreads();

    int e = blockIdx.x * blockDim.x + threadIdx.x;
    if (e >= N_EDGES) return;

    int s = ei[e];
    int d = ei[N_EDGES + e];

    float4 l4 = *reinterpret_cast<const float4*>(&g_sl[s * 4]);
    float4 r4 = *reinterpret_cast<const float4*>(&g_sr[d * 4]);
    float lv[4] = {l4.x, l4.y, l4.z, l4.w};
    float rv[4] = {r4.x, r4.y, r4.z, r4.w};

    float efv[16];
    const float4* ef4 = reinterpret_cast<const float4*>(ef + (size_t)e * 16);
#pragma unroll
    for (int q = 0; q < 4; q++) {
        float4 t = ef4[q];
        efv[q * 4 + 0] = t.x; efv[q * 4 + 1] = t.y;
        efv[q * 4 + 2] = t.z; efv[q * 4 + 3] = t.w;
    }

    float att[4];
#pragma unroll
    for (int hh = 0; hh < 4; hh++) {
        float x = lv[hh] + rv[hh];
        x = x > 0.0f ? x : 0.2f * x;           // leaky_relu(0.2)
        float dot = 0.0f;
#pragma unroll
        for (int q = 0; q < 16; q++) dot += efv[q] * sWe[hh * 16 + q];
        att[hh] = x + dot;
    }

    int pos = atomicAdd(&g_cursor[d], 1);
    reinterpret_cast<float4*>(g_sattn)[pos] =
        make_float4(att[0], att[1], att[2], att[3]);
    g_ssrc[pos] = s;
}

// ---------------- K5: gather aggregate + softmax + GELU + LayerNorm ----------
__device__ __forceinline__ float hsel(float4 t, int head) {
    return head == 0 ? t.x : head == 1 ? t.y : head == 2 ? t.z : t.w;
}

__global__ void __launch_bounds__(256) k_agg_final(const float* __restrict__ ln_s,
                                                   const float* __restrict__ ln_b,
                                                   float* __restrict__ out) {
    int gw   = (blockIdx.x * blockDim.x + threadIdx.x) >> 5;
    int lane = threadIdx.x & 31;
    if (gw >= N_NODES) return;

    int beg = g_offs[gw];
    int end = g_offs[gw + 1];

    const float4* attn4 = reinterpret_cast<const float4*>(g_sattn);
    const uint2*  wh2   = reinterpret_cast<const uint2*>(g_Wh);

    // pass A: per-head max
    float4 mx = make_float4(-1e9f, -1e9f, -1e9f, -1e9f);
    for (int i = beg + lane; i < end; i += 32) {
        float4 t = attn4[i];
        mx.x = fmaxf(mx.x, t.x); mx.y = fmaxf(mx.y, t.y);
        mx.z = fmaxf(mx.z, t.z); mx.w = fmaxf(mx.w, t.w);
    }
#pragma unroll
    for (int o = 16; o > 0; o >>= 1) {
        mx.x = fmaxf(mx.x, __shfl_xor_sync(0xffffffffu, mx.x, o));
        mx.y = fmaxf(mx.y, __shfl_xor_sync(0xffffffffu, mx.y, o));
        mx.z = fmaxf(mx.z, __shfl_xor_sync(0xffffffffu, mx.z, o));
        mx.w = fmaxf(mx.w, __shfl_xor_sync(0xffffffffu, mx.w, o));
    }

    // pass B: per-head denom
    float4 dn = make_float4(0.f, 0.f, 0.f, 0.f);
    for (int i = beg + lane; i < end; i += 32) {
        float4 t = attn4[i];
        dn.x += __expf(t.x - mx.x); dn.y += __expf(t.y - mx.y);
        dn.z += __expf(t.z - mx.z); dn.w += __expf(t.w - mx.w);
    }
#pragma unroll
    for (int o = 16; o > 0; o >>= 1) {
        dn.x += __shfl_xor_sync(0xffffffffu, dn.x, o);
        dn.y += __shfl_xor_sync(0xffffffffu, dn.y, o);
        dn.z += __shfl_xor_sync(0xffffffffu, dn.z, o);
        dn.w += __shfl_xor_sync(0xffffffffu, dn.w, o);
    }

    // pass C: weighted gather (lane owns cols 4*lane..4*lane+3; head = lane/8)
    const int head  = lane >> 3;
    const float mxh = hsel(mx, head);
    const float dnh = hsel(dn, head);

    float acc0 = 0.f, acc1 = 0.f, acc2 = 0.f, acc3 = 0.f;
    int i = beg;
    for (; i + 3 < end; i += 4) {             // MLP=4 gathers in flight
        int s0 = g_ssrc[i], s1 = g_ssrc[i + 1], s2 = g_ssrc[i + 2], s3 = g_ssrc[i + 3];
        float4 t0 = attn4[i],     t1 = attn4[i + 1];
        float4 t2 = attn4[i + 2], t3 = attn4[i + 3];
        uint2 p0 = wh2[s0 * 32 + lane];
        uint2 p1 = wh2[s1 * 32 + lane];
        uint2 p2 = wh2[s2 * 32 + lane];
        uint2 p3 = wh2[s3 * 32 + lane];
        float sc0 = __expf(hsel(t0, head) - mxh);
        float sc1 = __expf(hsel(t1, head) - mxh);
        float sc2 = __expf(hsel(t2, head) - mxh);
        float sc3 = __expf(hsel(t3, head) - mxh);
        float2 a0 = __half22float2(*reinterpret_cast<__half2*>(&p0.x));
        float2 b0 = __half22float2(*reinterpret_cast<__half2*>(&p0.y));
        float2 a1 = __half22float2(*reinterpret_cast<__half2*>(&p1.x));
        float2 b1 = __half22float2(*reinterpret_cast<__half2*>(&p1.y));
        float2 a2 = __half22float2(*reinterpret_cast<__half2*>(&p2.x));
        float2 b2 = __half22float2(*reinterpret_cast<__half2*>(&p2.y));
        float2 a3 = __half22float2(*reinterpret_cast<__half2*>(&p3.x));
        float2 b3 = __half22float2(*reinterpret_cast<__half2*>(&p3.y));
        acc0 += a0.x * sc0 + a1.x * sc1 + a2.x * sc2 + a3.x * sc3;
        acc1 += a0.y * sc0 + a1.y * sc1 + a2.y * sc2 + a3.y * sc3;
        acc2 += b0.x * sc0 + b1.x * sc1 + b2.x * sc2 + b3.x * sc3;
        acc3 += b0.y * sc0 + b1.y * sc1 + b2.y * sc2 + b3.y * sc3;
    }
    for (; i < end; i++) {
        int s = g_ssrc[i];
        float4 t = attn4[i];
        float sc = __expf(hsel(t, head) - mxh);
        uint2 p = wh2[s * 32 + lane];
        float2 fa = __half22float2(*reinterpret_cast<__half2*>(&p.x));
        float2 fb = __half22float2(*reinterpret_cast<__half2*>(&p.y));
        acc0 += fa.x * sc; acc1 += fa.y * sc; acc2 += fb.x * sc; acc3 += fb.y * sc;
    }

    float inv = 1.0f / (dnh + 1e-9f);
    float x0 = acc0 * inv, x1 = acc1 * inv, x2 = acc2 * inv, x3 = acc3 * inv;

    // exact GELU
    const float kc = 0.70710678118654752f;
    x0 = 0.5f * x0 * (1.0f + erff(x0 * kc));
    x1 = 0.5f * x1 * (1.0f + erff(x1 * kc));
    x2 = 0.5f * x2 * (1.0f + erff(x2 * kc));
    x3 = 0.5f * x3 * (1.0f + erff(x3 * kc));

    // LayerNorm over 128
    float ssum = x0 + x1 + x2 + x3;
#pragma unroll
    for (int o = 16; o > 0; o >>= 1) ssum += __shfl_xor_sync(0xffffffffu, ssum, o);
    float mu = ssum * (1.0f / 128.0f);

    float c0 = x0 - mu, c1 = x1 - mu, c2 = x2 - mu, c3 = x3 - mu;
    float vsum = c0 * c0 + c1 * c1 + c2 * c2 + c3 * c3;
#pragma unroll
    for (int o = 16; o > 0; o >>= 1) vsum += __shfl_xor_sync(0xffffffffu, vsum, o);
    float rstd = rsqrtf(vsum * (1.0f / 128.0f) + 1e-5f);

    float4 g = reinterpret_cast<const float4*>(ln_s)[lane];
    float4 b = reinterpret_cast<const float4*>(ln_b)[lane];
    float4 o4;
    o4.x = c0 * rstd * g.x + b.x;
    o4.y = c1 * rstd * g.y + b.y;
    o4.z = c2 * rstd * g.z + b.z;
    o4.w = c3 * rstd * g.w + b.w;
    reinterpret_cast<float4*>(out + (size_t)gw * 128)[lane] = o4;
}

// ---------------- launch -----------------------------------------------------
extern "C" void kernel_launch(void* const* d_in, const int* in_sizes, int n_in,
                              void* d_out, int out_size) {
    const float* h    = (const float*)d_in[0];
    const int*   ei   = (const int*)d_in[1];
    const float* ef   = (const float*)d_in[2];
    const float* W    = (const float*)d_in[3];
    const float* We   = (const float*)d_in[4];
    const float* a    = (const float*)d_in[5];
    const float* ln_s = (const float*)d_in[6];
    const float* ln_b = (const float*)d_in[7];
    float* out = (float*)d_out;

    k_zero<<<NB_CNT, 256>>>();
    k_count<<<(N_EDGES + 255) / 256, 256>>>(ei);
    k_scan_fused<<<NB_CNT, 256>>>();
    k_gemm<<<(N_NODES + 127) / 128, 256>>>(h, W, a);
    k_attn_fill<<<(N_EDGES + 255) / 256, 256>>>(ei, ef, We);
    k_agg_final<<<(N_NODES * 32 + 255) / 256, 256>>>(ln_s, ln_b, out);
}

// round 13
// speedup vs baseline: 1.0816x; 1.0816x over previous
#include <cuda_runtime.h>
#include <cuda_fp16.h>

#define N_NODES 50000
#define N_EDGES 640000
#define NB_CNT ((N_NODES + 255) / 256)   // 196 scan blocks
// IN_DIM = OUT_DIM = 128, H = 4, D = 32

// ---------------- scratch (device globals; no allocation allowed) ------------
__device__ __align__(16) __half g_Wh[N_NODES * 128];   // fp16 Wh
__device__ __align__(16) float g_sl[N_NODES * 4];
__device__ __align__(16) float g_sr[N_NODES * 4];
__device__ __align__(16) float g_sattn[N_EDGES * 4];   // attn logits, dst-sorted
__device__ int g_ssrc[N_EDGES];                        // src node, dst-sorted
__device__ int g_cnt[N_NODES];
__device__ int g_offs[N_NODES + 1];
__device__ int g_cursor[N_NODES];
__device__ unsigned long long g_scanstate[NB_CNT];     // flag<<62 | sum

// ---------------- K0: zero counters + scan state -----------------------------
__global__ void __launch_bounds__(256) k_zero() {
    int i = blockIdx.x * blockDim.x + threadIdx.x;
    if (i < N_NODES) g_cnt[i] = 0;
    if (i < NB_CNT)  g_scanstate[i] = 0ull;
}

// ---------------- K1: count incoming edges per node ---------------------------
__global__ void __launch_bounds__(256) k_count(const int* __restrict__ ei) {
    int e = blockIdx.x * blockDim.x + threadIdx.x;
    if (e < N_EDGES) atomicAdd(&g_cnt[ei[N_EDGES + e]], 1);
}

// ---------------- K2: single-kernel exclusive scan (decoupled lookback) ------
__global__ void __launch_bounds__(256) k_scan_fused() {
    __shared__ int swsum[8];
    __shared__ int s_running;
    const int t = threadIdx.x, b = blockIdx.x;
    const int lane = t & 31, w = t >> 5;
    const int i = b * 256 + t;

    int c = (i < N_NODES) ? g_cnt[i] : 0;
    int x = c;
#pragma unroll
    for (int o = 1; o < 32; o <<= 1) {
        int v = __shfl_up_sync(0xffffffffu, x, o);
        if (lane >= o) x += v;
    }
    if (lane == 31) swsum[w] = x;
    __syncthreads();
    if (w == 0) {
        int y = (lane < 8) ? swsum[lane] : 0;
#pragma unroll
        for (int o = 1; o < 8; o <<= 1) {
            int v = __shfl_up_sync(0xffffffffu, y, o);
            if (lane >= o) y += v;
        }
        if (lane < 8) swsum[lane] = y;
    }
    __syncthreads();
    const int incl  = x + (w > 0 ? swsum[w - 1] : 0);
    const int total = swsum[7];

    if (t == 0) {
        unsigned long long pub =
            ((unsigned long long)(b == 0 ? 2 : 1) << 62) | (unsigned)total;
        __threadfence();
        atomicExch(&g_scanstate[b], pub);

        int run = 0;
        if (b > 0) {
            int j = b - 1;
            while (true) {
                unsigned long long s = atomicAdd(&g_scanstate[j], 0ull);
                unsigned f = (unsigned)(s >> 62);
                if (f == 0) continue;
                run += (int)(s & 0xffffffffull);
                if (f == 2) break;
                j--;
            }
            unsigned long long pub2 = (2ull << 62) | (unsigned)(run + total);
            atomicExch(&g_scanstate[b], pub2);
        }
        s_running = run;
    }
    __syncthreads();

    int off = s_running + incl - c;
    if (i < N_NODES) {
        g_offs[i]   = off;
        g_cursor[i] = off;
    }
    if (b == gridDim.x - 1 && t == 255) g_offs[N_NODES] = s_running + incl;
}

// ---------------- K3: Wh = h @ W^T via fp16 MMA (64-row tiles, high occ) -----
// Block tile 64x128, 8 warps = 4(m) x 2(n); warp tile 16 rows x 64 cols
// = 1 m16 tile x 8 n8 tiles -> 32 acc regs/thread.
__device__ __forceinline__ unsigned smem_u32(const void* p) {
    return (unsigned)__cvta_generic_to_shared(p);
}

__global__ void __launch_bounds__(256, 3) k_gemm(const float* __restrict__ h,
                                                 const float* __restrict__ W,
                                                 const float* __restrict__ a) {
    __shared__ __half As[64 * 72];    // 64 rows x 72 (padded) halfs
    __shared__ __half Bs[128 * 72];   // Bs[n][k] = W[n][k]
    const int tid  = threadIdx.x;
    const int lane = tid & 31;
    const int warp = tid >> 5;
    const int m0 = (warp >> 1) * 16;      // warp row base within block
    const int n0 = (warp & 1) * 64;       // warp col base within block
    const int rowbase = blockIdx.x * 64;

    float acc[8][4];
#pragma unroll
    for (int nt = 0; nt < 8; nt++)
#pragma unroll
        for (int q = 0; q < 4; q++) acc[nt][q] = 0.0f;

    const float4* h4 = reinterpret_cast<const float4*>(h);
    const float4* W4 = reinterpret_cast<const float4*>(W);

    for (int phase = 0; phase < 2; phase++) {
        __syncthreads();
        {
            int r  = tid >> 4;       // 0..15
            int c4 = tid & 15;       // float4 index within 64 cols
#pragma unroll
            for (int it = 0; it < 4; it++) {   // 64 rows of A
                int row  = r + it * 16;
                int grow = rowbase + row;
                if (grow >= N_NODES) grow = N_NODES - 1;
                float4 v = h4[grow * 32 + phase * 16 + c4];
                __half2* dst = reinterpret_cast<__half2*>(&As[row * 72 + c4 * 4]);
                dst[0] = __floats2half2_rn(v.x, v.y);
                dst[1] = __floats2half2_rn(v.z, v.w);
            }
#pragma unroll
            for (int it = 0; it < 8; it++) {   // 128 rows of B
                int n = r + it * 16;
                float4 v = W4[n * 32 + phase * 16 + c4];
                __half2* dst = reinterpret_cast<__half2*>(&Bs[n * 72 + c4 * 4]);
                dst[0] = __floats2half2_rn(v.x, v.y);
                dst[1] = __floats2half2_rn(v.z, v.w);
            }
        }
        __syncthreads();

#pragma unroll
        for (int ks = 0; ks < 4; ks++) {
            const int k = ks * 16;
            unsigned af[4];
            {
                int row = m0 + (lane & 15);
                int col = k + (lane >> 4) * 8;
                unsigned addr = smem_u32(&As[row * 72 + col]);
                asm volatile(
                    "ldmatrix.sync.aligned.m8n8.x4.shared.b16 {%0,%1,%2,%3}, [%4];"
                    : "=r"(af[0]), "=r"(af[1]), "=r"(af[2]), "=r"(af[3])
                    : "r"(addr));
            }
            unsigned bf[8][2];
#pragma unroll
            for (int nt2 = 0; nt2 < 4; nt2++) {
                int n   = n0 + nt2 * 16 + (lane >> 4) * 8 + (lane & 7);
                int col = k + ((lane >> 3) & 1) * 8;
                unsigned addr = smem_u32(&Bs[n * 72 + col]);
                unsigned r0, r1, r2, r3;
                asm volatile(
                    "ldmatrix.sync.aligned.m8n8.x4.shared.b16 {%0,%1,%2,%3}, [%4];"
                    : "=r"(r0), "=r"(r1), "=r"(r2), "=r"(r3)
                    : "r"(addr));
                bf[nt2 * 2][0]     = r0; bf[nt2 * 2][1]     = r1;
                bf[nt2 * 2 + 1][0] = r2; bf[nt2 * 2 + 1][1] = r3;
            }
#pragma unroll
            for (int nt = 0; nt < 8; nt++) {
                asm volatile(
                    "mma.sync.aligned.m16n8k16.row.col.f32.f16.f16.f32 "
                    "{%0,%1,%2,%3}, {%4,%5,%6,%7}, {%8,%9}, {%0,%1,%2,%3};"
                    : "+f"(acc[nt][0]), "+f"(acc[nt][1]),
                      "+f"(acc[nt][2]), "+f"(acc[nt][3])
                    : "r"(af[0]), "r"(af[1]), "r"(af[2]), "r"(af[3]),
                      "r"(bf[nt][0]), "r"(bf[nt][1]));
            }
        }
    }

    // ---- epilogue: Wh fp16 stores + fused s_l/s_r from fp32 accumulators ----
    // frag layout: d0,d1 -> row lane/4, cols 2(lane%4)+{0,1}; d2,d3 -> row+8.
    const int h0 = (warp & 1) * 2;    // this warp's heads: h0, h0+1
    const int cb = (lane & 3) * 2;

    int r0 = rowbase + m0 + (lane >> 2);
    int r1 = r0 + 8;
#pragma unroll
    for (int nt = 0; nt < 8; nt++) {
        int col = n0 + nt * 8 + cb;
        if (r0 < N_NODES)
            *reinterpret_cast<__half2*>(&g_Wh[r0 * 128 + col]) =
                __floats2half2_rn(acc[nt][0], acc[nt][1]);
        if (r1 < N_NODES)
            *reinterpret_cast<__half2*>(&g_Wh[r1 * 128 + col]) =
                __floats2half2_rn(acc[nt][2], acc[nt][3]);
    }

    float sl[2] = {0.f, 0.f}, sr[2] = {0.f, 0.f};   // row r0, heads h0,h0+1
    float ul[2] = {0.f, 0.f}, ur[2] = {0.f, 0.f};   // row r1
#pragma unroll
    for (int nt = 0; nt < 8; nt++) {
        int hi = nt >> 2;
        int hh = h0 + hi;
        int d  = (nt & 3) * 8 + cb;                 // dim within head
        float al0 = a[hh * 64 + d],      al1 = a[hh * 64 + d + 1];
        float ar0 = a[hh * 64 + 32 + d], ar1 = a[hh * 64 + 32 + d + 1];
        sl[hi] += acc[nt][0] * al0 + acc[nt][1] * al1;
        sr[hi] += acc[nt][0] * ar0 + acc[nt][1] * ar1;
        ul[hi] += acc[nt][2] * al0 + acc[nt][3] * al1;
        ur[hi] += acc[nt][2] * ar0 + acc[nt][3] * ar1;
    }
#pragma unroll
    for (int o = 1; o < 4; o <<= 1) {
#pragma unroll
        for (int hi = 0; hi < 2; hi++) {
            sl[hi] += __shfl_xor_sync(0xffffffffu, sl[hi], o);
            sr[hi] += __shfl_xor_sync(0xffffffffu, sr[hi], o);
            ul[hi] += __shfl_xor_sync(0xffffffffu, ul[hi], o);
            ur[hi] += __shfl_xor_sync(0xffffffffu, ur[hi], o);
        }
    }
    if ((lane & 3) == 0) {
        if (r0 < N_NODES) {
            g_sl[r0 * 4 + h0]     = sl[0];
            g_sl[r0 * 4 + h0 + 1] = sl[1];
            g_sr[r0 * 4 + h0]     = sr[0];
            g_sr[r0 * 4 + h0 + 1] = sr[1];
        }
        if (r1 < N_NODES) {
            g_sl[r1 * 4 + h0]     = ul[0];
            g_sl[r1 * 4 + h0 + 1] = ul[1];
            g_sr[r1 * 4 + h0]     = ur[0];
            g_sr[r1 * 4 + h0 + 1] = ur[1];
        }
    }
}

// ---------------- K4: attention logits, written in dst-sorted order ----------
__global__ void __launch_bounds__(256) k_attn_fill(const int* __restrict__ ei,
                                                   const float* __restrict__ ef,
                                                   const float* __restrict__ We) {
    __shared__ float sWe[64];
    if (threadIdx.x < 64) sWe[threadIdx.x] = We[threadIdx.x];
    __syncthreads();

    int e = blockIdx.x * blockDim.x + threadIdx.x;
    if (e >= N_EDGES) return;

    int s = ei[e];
    int d = ei[N_EDGES + e];

    float4 l4 = *reinterpret_cast<const float4*>(&g_sl[s * 4]);
    float4 r4 = *reinterpret_cast<const float4*>(&g_sr[d * 4]);
    float lv[4] = {l4.x, l4.y, l4.z, l4.w};
    float rv[4] = {r4.x, r4.y, r4.z, r4.w};

    float efv[16];
    const float4* ef4 = reinterpret_cast<const float4*>(ef + (size_t)e * 16);
#pragma unroll
    for (int q = 0; q < 4; q++) {
        float4 t = ef4[q];
        efv[q * 4 + 0] = t.x; efv[q * 4 + 1] = t.y;
        efv[q * 4 + 2] = t.z; efv[q * 4 + 3] = t.w;
    }

    float att[4];
#pragma unroll
    for (int hh = 0; hh < 4; hh++) {
        float x = lv[hh] + rv[hh];
        x = x > 0.0f ? x : 0.2f * x;           // leaky_relu(0.2)
        float dot = 0.0f;
#pragma unroll
        for (int q = 0; q < 16; q++) dot += efv[q] * sWe[hh * 16 + q];
        att[hh] = x + dot;
    }

    int pos = atomicAdd(&g_cursor[d], 1);
    reinterpret_cast<float4*>(g_sattn)[pos] =
        make_float4(att[0], att[1], att[2], att[3]);
    g_ssrc[pos] = s;
}

// ---------------- K5: gather aggregate + softmax + GELU + LayerNorm ----------
__device__ __forceinline__ float hsel(float4 t, int head) {
    return head == 0 ? t.x : head == 1 ? t.y : head == 2 ? t.z : t.w;
}

__global__ void __launch_bounds__(256) k_agg_final(const float* __restrict__ ln_s,
                                                   const float* __restrict__ ln_b,
                                                   float* __restrict__ out) {
    int gw   = (blockIdx.x * blockDim.x + threadIdx.x) >> 5;
    int lane = threadIdx.x & 31;
    if (gw >= N_NODES) return;

    int beg = g_offs[gw];
    int end = g_offs[gw + 1];

    const float4* attn4 = reinterpret_cast<const float4*>(g_sattn);
    const uint2*  wh2   = reinterpret_cast<const uint2*>(g_Wh);

    // pass A: per-head max
    float4 mx = make_float4(-1e9f, -1e9f, -1e9f, -1e9f);
    for (int i = beg + lane; i < end; i += 32) {
        float4 t = attn4[i];
        mx.x = fmaxf(mx.x, t.x); mx.y = fmaxf(mx.y, t.y);
        mx.z = fmaxf(mx.z, t.z); mx.w = fmaxf(mx.w, t.w);
    }
#pragma unroll
    for (int o = 16; o > 0; o >>= 1) {
        mx.x = fmaxf(mx.x, __shfl_xor_sync(0xffffffffu, mx.x, o));
        mx.y = fmaxf(mx.y, __shfl_xor_sync(0xffffffffu, mx.y, o));
        mx.z = fmaxf(mx.z, __shfl_xor_sync(0xffffffffu, mx.z, o));
        mx.w = fmaxf(mx.w, __shfl_xor_sync(0xffffffffu, mx.w, o));
    }

    // pass B: per-head denom
    float4 dn = make_float4(0.f, 0.f, 0.f, 0.f);
    for (int i = beg + lane; i < end; i += 32) {
        float4 t = attn4[i];
        dn.x += __expf(t.x - mx.x); dn.y += __expf(t.y - mx.y);
        dn.z += __expf(t.z - mx.z); dn.w += __expf(t.w - mx.w);
    }
#pragma unroll
    for (int o = 16; o > 0; o >>= 1) {
        dn.x += __shfl_xor_sync(0xffffffffu, dn.x, o);
        dn.y += __shfl_xor_sync(0xffffffffu, dn.y, o);
        dn.z += __shfl_xor_sync(0xffffffffu, dn.z, o);
        dn.w += __shfl_xor_sync(0xffffffffu, dn.w, o);
    }

    // pass C: weighted gather (lane owns cols 4*lane..4*lane+3; head = lane/8)
    const int head  = lane >> 3;
    const float mxh = hsel(mx, head);
    const float dnh = hsel(dn, head);

    float acc0 = 0.f, acc1 = 0.f, acc2 = 0.f, acc3 = 0.f;
    int i = beg;
    for (; i + 3 < end; i += 4) {             // MLP=4 gathers in flight
        int s0 = g_ssrc[i], s1 = g_ssrc[i + 1], s2 = g_ssrc[i + 2], s3 = g_ssrc[i + 3];
        float4 t0 = attn4[i],     t1 = attn4[i + 1];
        float4 t2 = attn4[i + 2], t3 = attn4[i + 3];
        uint2 p0 = wh2[s0 * 32 + lane];
        uint2 p1 = wh2[s1 * 32 + lane];
        uint2 p2 = wh2[s2 * 32 + lane];
        uint2 p3 = wh2[s3 * 32 + lane];
        float sc0 = __expf(hsel(t0, head) - mxh);
        float sc1 = __expf(hsel(t1, head) - mxh);
        float sc2 = __expf(hsel(t2, head) - mxh);
        float sc3 = __expf(hsel(t3, head) - mxh);
        float2 a0 = __half22float2(*reinterpret_cast<__half2*>(&p0.x));
        float2 b0 = __half22float2(*reinterpret_cast<__half2*>(&p0.y));
        float2 a1 = __half22float2(*reinterpret_cast<__half2*>(&p1.x));
        float2 b1 = __half22float2(*reinterpret_cast<__half2*>(&p1.y));
        float2 a2 = __half22float2(*reinterpret_cast<__half2*>(&p2.x));
        float2 b2 = __half22float2(*reinterpret_cast<__half2*>(&p2.y));
        float2 a3 = __half22float2(*reinterpret_cast<__half2*>(&p3.x));
        float2 b3 = __half22float2(*reinterpret_cast<__half2*>(&p3.y));
        acc0 += a0.x * sc0 + a1.x * sc1 + a2.x * sc2 + a3.x * sc3;
        acc1 += a0.y * sc0 + a1.y * sc1 + a2.y * sc2 + a3.y * sc3;
        acc2 += b0.x * sc0 + b1.x * sc1 + b2.x * sc2 + b3.x * sc3;
        acc3 += b0.y * sc0 + b1.y * sc1 + b2.y * sc2 + b3.y * sc3;
    }
    for (; i < end; i++) {
        int s = g_ssrc[i];
        float4 t = attn4[i];
        float sc = __expf(hsel(t, head) - mxh);
        uint2 p = wh2[s * 32 + lane];
        float2 fa = __half22float2(*reinterpret_cast<__half2*>(&p.x));
        float2 fb = __half22float2(*reinterpret_cast<__half2*>(&p.y));
        acc0 += fa.x * sc; acc1 += fa.y * sc; acc2 += fb.x * sc; acc3 += fb.y * sc;
    }

    float inv = 1.0f / (dnh + 1e-9f);
    float x0 = acc0 * inv, x1 = acc1 * inv, x2 = acc2 * inv, x3 = acc3 * inv;

    // exact GELU
    const float kc = 0.70710678118654752f;
    x0 = 0.5f * x0 * (1.0f + erff(x0 * kc));
    x1 = 0.5f * x1 * (1.0f + erff(x1 * kc));
    x2 = 0.5f * x2 * (1.0f + erff(x2 * kc));
    x3 = 0.5f * x3 * (1.0f + erff(x3 * kc));

    // LayerNorm over 128
    float ssum = x0 + x1 + x2 + x3;
#pragma unroll
    for (int o = 16; o > 0; o >>= 1) ssum += __shfl_xor_sync(0xffffffffu, ssum, o);
    float mu = ssum * (1.0f / 128.0f);

    float c0 = x0 - mu, c1 = x1 - mu, c2 = x2 - mu, c3 = x3 - mu;
    float vsum = c0 * c0 + c1 * c1 + c2 * c2 + c3 * c3;
#pragma unroll
    for (int o = 16; o > 0; o >>= 1) vsum += __shfl_xor_sync(0xffffffffu, vsum, o);
    float rstd = rsqrtf(vsum * (1.0f / 128.0f) + 1e-5f);

    float4 g = reinterpret_cast<const float4*>(ln_s)[lane];
    float4 b = reinterpret_cast<const float4*>(ln_b)[lane];
    float4 o4;
    o4.x = c0 * rstd * g.x + b.x;
    o4.y = c1 * rstd * g.y + b.y;
    o4.z = c2 * rstd * g.z + b.z;
    o4.w = c3 * rstd * g.w + b.w;
    reinterpret_cast<float4*>(out + (size_t)gw * 128)[lane] = o4;
}

// ---------------- launch -----------------------------------------------------
extern "C" void kernel_launch(void* const* d_in, const int* in_sizes, int n_in,
                              void* d_out, int out_size) {
    const float* h    = (const float*)d_in[0];
    const int*   ei   = (const int*)d_in[1];
    const float* ef   = (const float*)d_in[2];
    const float* W    = (const float*)d_in[3];
    const float* We   = (const float*)d_in[4];
    const float* a    = (const float*)d_in[5];
    const float* ln_s = (const float*)d_in[6];
    const float* ln_b = (const float*)d_in[7];
    float* out = (float*)d_out;

    k_zero<<<NB_CNT, 256>>>();
    k_count<<<(N_EDGES + 255) / 256, 256>>>(ei);
    k_scan_fused<<<NB_CNT, 256>>>();
    k_gemm<<<(N_NODES + 63) / 64, 256>>>(h, W, a);
    k_attn_fill<<<(N_EDGES + 255) / 256, 256>>>(ei, ef, We);
    k_agg_final<<<(N_NODES * 32 + 255) / 256, 256>>>(ln_s, ln_b, out);
}